// round 9
// baseline (speedup 1.0000x reference)
#include <cuda_runtime.h>
#include <math.h>

// Problem dims
#define Bq      32
#define Dq      512
#define Hq      1024
#define FOURH   4096
#define KTOT    1536            // H + D combined reduction dim
#define KSPLIT  8
#define KCHUNK  (KTOT / KSPLIT) // 192
#define PSPLIT  64              // plastic i-splits per batch
#define PCHUNK  (Hq / PSPLIT)   // 16

#define NPLAST  (Bq * PSPLIT)   // 2048 plastic blocks
#define NGEMM   (32 * KSPLIT)   // 256 gemm blocks

// Scratch (static __device__ — no allocation)
__device__ float g_part[KSPLIT][Bq * FOURH];        // GEMM partials (4 MB)
__device__ float g_plastic_part[NPLAST * Hq];       // plastic partials (8 MB)
__device__ float g_tanhg[Bq * Hq];                  // tanh(cell gate) (128 KB)

// ---------------------------------------------------------------------------
// K_gemm: gates partials. C[b][j] = sum_k A[k][b]*W[k][j]
//   32-row k-tiles, float4 W loads, 6 syncs per block.
// ---------------------------------------------------------------------------
__global__ __launch_bounds__(256)
void k_gemm(const float* __restrict__ x,  const float* __restrict__ h0,
            const float* __restrict__ Wh, const float* __restrict__ Wx)
{
    __shared__ float Ws[32][128];
    __shared__ float As[32][32];

    const int jt  = blockIdx.x & 31;    // j tile (128 wide)
    const int ks  = blockIdx.x >> 5;    // k split (0..7)
    const int tid = threadIdx.x;
    const int tj  = tid & 31;
    const int tb  = tid >> 5;

    float acc[4][4];
#pragma unroll
    for (int i = 0; i < 4; i++)
#pragma unroll
        for (int j = 0; j < 4; j++) acc[i][j] = 0.f;

    const int k0base = ks * KCHUNK;
    const int jbase  = jt * 128;

    const float4* Wh4 = (const float4*)Wh;   // row stride FOURH/4 = 1024
    const float4* Wx4 = (const float4*)Wx;

    for (int t = 0; t < KCHUNK / 32; t++) {
        const int k0 = k0base + t * 32;
        __syncthreads();
        // W tile: 32 rows x 128 cols = 1024 float4, 4 per thread
#pragma unroll
        for (int s = 0; s < 4; s++) {
            int lin = s * 256 + tid;
            int kk = lin >> 5, j4 = lin & 31;
            int k = k0 + kk;
            float4 w = (k < Hq) ? Wh4[(size_t)k * 1024 + (jbase >> 2) + j4]
                                : Wx4[(size_t)(k - Hq) * 1024 + (jbase >> 2) + j4];
            *(float4*)&Ws[kk][j4 * 4] = w;
        }
        // A tile: 32 k-rows x 32 b = 1024 floats, 4 per thread
#pragma unroll
        for (int s = 0; s < 4; s++) {
            int lin = s * 256 + tid;
            int kk = lin >> 5, bb = lin & 31;
            int k = k0 + kk;
            As[kk][bb] = (k < Hq) ? h0[bb * Hq + k] : x[bb * Dq + (k - Hq)];
        }
        __syncthreads();
#pragma unroll
        for (int kk = 0; kk < 32; kk++) {
            float4 a = *(const float4*)&As[kk][tb * 4];
            float4 w = *(const float4*)&Ws[kk][tj * 4];
            acc[0][0] += a.x*w.x; acc[0][1] += a.x*w.y; acc[0][2] += a.x*w.z; acc[0][3] += a.x*w.w;
            acc[1][0] += a.y*w.x; acc[1][1] += a.y*w.y; acc[1][2] += a.y*w.z; acc[1][3] += a.y*w.w;
            acc[2][0] += a.z*w.x; acc[2][1] += a.z*w.y; acc[2][2] += a.z*w.z; acc[2][3] += a.z*w.w;
            acc[3][0] += a.w*w.x; acc[3][1] += a.w*w.y; acc[3][2] += a.w*w.z; acc[3][3] += a.w*w.w;
        }
    }

    float* outp = g_part[ks];
#pragma unroll
    for (int bb = 0; bb < 4; bb++) {
        int b = tb * 4 + bb;
        int base = b * FOURH + jbase + tj * 4;
        *(float4*)&outp[base] = make_float4(acc[bb][0], acc[bb][1], acc[bb][2], acc[bb][3]);
    }
}

// ---------------------------------------------------------------------------
// K_plastic: occupancy-first streaming (hebb-shaped).
// partial[b,sp,h] = sum_{i in 16-chunk sp} h0[b,i]*alpha[i,h]*Hebb0[b,i,h]
// 2-row body -> 4 float4 loads, ~34 regs, 6 blocks/SM (48 warps).
// ---------------------------------------------------------------------------
__global__ __launch_bounds__(256, 6)
void k_plastic(const float* __restrict__ h0, const float* __restrict__ alpha,
               const float* __restrict__ Hebb0)
{
    const int b  = blockIdx.x >> 6;
    const int sp = blockIdx.x & 63;
    const int i0 = sp * PCHUNK;
    const int t  = threadIdx.x;

    const float4* Ap  = (const float4*)(alpha + (size_t)i0 * Hq) + t;
    const float4* Hp  = (const float4*)(Hebb0 + ((size_t)b * Hq + i0) * Hq) + t;
    const float*  h0p = h0 + b * Hq + i0;

    float4 acc = make_float4(0.f, 0.f, 0.f, 0.f);
#pragma unroll 1
    for (int i = 0; i < PCHUNK; i += 2) {
        float4 a0 = Ap[(size_t)(i + 0) * 256];
        float4 v0 = Hp[(size_t)(i + 0) * 256];
        float4 a1 = Ap[(size_t)(i + 1) * 256];
        float4 v1 = Hp[(size_t)(i + 1) * 256];
        float s0 = h0p[i + 0];
        float s1 = h0p[i + 1];
        acc.x = fmaf(s0, a0.x * v0.x, acc.x);
        acc.y = fmaf(s0, a0.y * v0.y, acc.y);
        acc.z = fmaf(s0, a0.z * v0.z, acc.z);
        acc.w = fmaf(s0, a0.w * v0.w, acc.w);
        acc.x = fmaf(s1, a1.x * v1.x, acc.x);
        acc.y = fmaf(s1, a1.y * v1.y, acc.y);
        acc.z = fmaf(s1, a1.z * v1.z, acc.z);
        acc.w = fmaf(s1, a1.w * v1.w, acc.w);
    }
    ((float4*)(g_plastic_part + (size_t)blockIdx.x * Hq))[t] = acc;
}

// ---------------------------------------------------------------------------
// K2: pointwise gates -> h1, c1, tanh_g
// ---------------------------------------------------------------------------
__global__ __launch_bounds__(256)
void pointwise_kernel(const float* __restrict__ c0, const float* __restrict__ bias,
                      float* __restrict__ out)
{
    const int idx = blockIdx.x * 256 + threadIdx.x;   // 0..32767
    const int b = idx >> 10, h = idx & 1023;

    float g4[4];
#pragma unroll
    for (int c = 0; c < 4; c++) {
        float v = bias[c * Hq + h];
        int base = b * FOURH + c * Hq + h;
#pragma unroll
        for (int s = 0; s < KSPLIT; s++) v += g_part[s][base];
        g4[c] = v;
    }
    float pl = 0.f;
#pragma unroll
    for (int s = 0; s < PSPLIT; s++)
        pl += g_plastic_part[(size_t)(b * PSPLIT + s) * Hq + h];
    g4[3] += pl;

    float fg = 1.f / (1.f + expf(-g4[0]));
    float ig = 1.f / (1.f + expf(-g4[1]));
    float og = 1.f / (1.f + expf(-g4[2]));
    float tg = tanhf(g4[3]);
    float c1 = fg * c0[idx] + ig * tg;
    float h1 = og * tanhf(c1);

    out[idx]           = h1;  // h1 block
    out[Bq * Hq + idx] = c1;  // c1 block
    g_tanhg[idx] = tg;
}

// ---------------------------------------------------------------------------
// K3: Hebb1[b,h,i] = clip(Hebb0[b,h,i] + eta*h0[b,h]*tanh_g[b,i], -1, 1)
// 4 rows per block, float4, streaming hints (R8-measured: 36us, 74% DRAM).
// ---------------------------------------------------------------------------
__global__ __launch_bounds__(256)
void hebb_kernel(const float* __restrict__ Hebb0, const float* __restrict__ h0,
                 const float* __restrict__ eta, float* __restrict__ HebbOut)
{
    const int r0 = (Bq * Hq - 4) - blockIdx.x * 4;   // reversed, 4-row group
    const int b  = r0 >> 10;
    const float e = eta[0];
    const int t = threadIdx.x;

    float4 tv = ((const float4*)(g_tanhg + (size_t)b * Hq))[t];

    const float4* in4 = (const float4*)(Hebb0   + (size_t)r0 * Hq) + t;
    float4*       o4  = (float4*)      (HebbOut + (size_t)r0 * Hq) + t;

    float c0f = e * h0[r0 + 0];
    float c1f = e * h0[r0 + 1];
    float c2f = e * h0[r0 + 2];
    float c3f = e * h0[r0 + 3];

    float4 v0 = __ldcs(in4 + 0 * 256);
    float4 v1 = __ldcs(in4 + 1 * 256);
    float4 v2 = __ldcs(in4 + 2 * 256);
    float4 v3 = __ldcs(in4 + 3 * 256);

    float4 o;
    o.x = fminf(1.f, fmaxf(-1.f, fmaf(c0f, tv.x, v0.x)));
    o.y = fminf(1.f, fmaxf(-1.f, fmaf(c0f, tv.y, v0.y)));
    o.z = fminf(1.f, fmaxf(-1.f, fmaf(c0f, tv.z, v0.z)));
    o.w = fminf(1.f, fmaxf(-1.f, fmaf(c0f, tv.w, v0.w)));
    __stcs(o4 + 0 * 256, o);
    o.x = fminf(1.f, fmaxf(-1.f, fmaf(c1f, tv.x, v1.x)));
    o.y = fminf(1.f, fmaxf(-1.f, fmaf(c1f, tv.y, v1.y)));
    o.z = fminf(1.f, fmaxf(-1.f, fmaf(c1f, tv.z, v1.z)));
    o.w = fminf(1.f, fmaxf(-1.f, fmaf(c1f, tv.w, v1.w)));
    __stcs(o4 + 1 * 256, o);
    o.x = fminf(1.f, fmaxf(-1.f, fmaf(c2f, tv.x, v2.x)));
    o.y = fminf(1.f, fmaxf(-1.f, fmaf(c2f, tv.y, v2.y)));
    o.z = fminf(1.f, fmaxf(-1.f, fmaf(c2f, tv.z, v2.z)));
    o.w = fminf(1.f, fmaxf(-1.f, fmaf(c2f, tv.w, v2.w)));
    __stcs(o4 + 2 * 256, o);
    o.x = fminf(1.f, fmaxf(-1.f, fmaf(c3f, tv.x, v3.x)));
    o.y = fminf(1.f, fmaxf(-1.f, fmaf(c3f, tv.y, v3.y)));
    o.z = fminf(1.f, fmaxf(-1.f, fmaf(c3f, tv.z, v3.z)));
    o.w = fminf(1.f, fmaxf(-1.f, fmaf(c3f, tv.w, v3.w)));
    __stcs(o4 + 3 * 256, o);
}

// ---------------------------------------------------------------------------
// Inputs: x, h0, c0, Hebb0, weight_h, weight_x, bias, alpha, eta
// Output: [h1 (B*H) | c1 (B*H) | Hebb1 (B*H*H)] float32
// ---------------------------------------------------------------------------
extern "C" void kernel_launch(void* const* d_in, const int* in_sizes, int n_in,
                              void* d_out, int out_size)
{
    const float* x     = (const float*)d_in[0];
    const float* h0    = (const float*)d_in[1];
    const float* c0    = (const float*)d_in[2];
    const float* Hebb0 = (const float*)d_in[3];
    const float* Wh    = (const float*)d_in[4];
    const float* Wx    = (const float*)d_in[5];
    const float* bias  = (const float*)d_in[6];
    const float* alpha = (const float*)d_in[7];
    const float* eta   = (const float*)d_in[8];
    float* out = (float*)d_out;

    k_gemm<<<NGEMM, 256>>>(x, h0, Wh, Wx);
    k_plastic<<<NPLAST, 256>>>(h0, alpha, Hebb0);
    pointwise_kernel<<<(Bq * Hq) / 256, 256>>>(c0, bias, out);
    hebb_kernel<<<(Bq * Hq) / 4, 256>>>(Hebb0, h0, eta, out + 2 * Bq * Hq);
}

// round 10
// speedup vs baseline: 1.0998x; 1.0998x over previous
#include <cuda_runtime.h>
#include <math.h>

// Problem dims
#define Bq      32
#define Dq      512
#define Hq      1024
#define FOURH   4096
#define KTOT    1536            // H + D combined reduction dim
#define KSPLIT  16
#define KCHUNK  (KTOT / KSPLIT) // 96
#define PSPLIT  64              // plastic i-splits per batch
#define PCHUNK  (Hq / PSPLIT)   // 16

#define NPLAST  (Bq * PSPLIT)   // 2048 plastic blocks
#define NGEMM   (32 * KSPLIT)   // 512 gemm blocks

// Scratch (static __device__ — no allocation)
__device__ float g_part[KSPLIT][Bq * FOURH];        // GEMM partials (8 MB)
__device__ float g_plastic_part[NPLAST * Hq];       // plastic partials (8 MB)
__device__ float g_tanhg[Bq * Hq];                  // tanh(cell gate) (128 KB)

// ---------------------------------------------------------------------------
// K_gemm: gates partials. C[b][j] = sum_k A[k][b]*W[k][j]
// 512 blocks (32 jt x 16 ks), 32-row k-tiles (3 per block).
// A staged TRANSPOSED: coalesced global reads, broadcast smem reads.
// ---------------------------------------------------------------------------
__global__ __launch_bounds__(256)
void k_gemm(const float* __restrict__ x,  const float* __restrict__ h0,
            const float* __restrict__ Wh, const float* __restrict__ Wx)
{
    __shared__ float Ws[32][128];
    __shared__ float As[32][33];   // [b][k], padded

    const int jt  = blockIdx.x & 31;    // j tile (128 wide)
    const int ks  = blockIdx.x >> 5;    // k split (0..15)
    const int tid = threadIdx.x;
    const int tj  = tid & 31;
    const int tb  = tid >> 5;

    float acc[4][4];
#pragma unroll
    for (int i = 0; i < 4; i++)
#pragma unroll
        for (int j = 0; j < 4; j++) acc[i][j] = 0.f;

    const int k0base = ks * KCHUNK;
    const int jbase  = jt * 128;

    const float4* Wh4 = (const float4*)Wh;   // row stride 1024 float4
    const float4* Wx4 = (const float4*)Wx;

    for (int t = 0; t < KCHUNK / 32; t++) {
        const int k0 = k0base + t * 32;
        __syncthreads();
        // W tile: 32 rows x 128 cols = 1024 float4, 4/thread, coalesced
#pragma unroll
        for (int s = 0; s < 4; s++) {
            int lin = s * 256 + tid;
            int kk = lin >> 5, j4 = lin & 31;
            int k = k0 + kk;
            float4 w = (k < Hq) ? Wh4[(size_t)k * 1024 + (jbase >> 2) + j4]
                                : Wx4[(size_t)(k - Hq) * 1024 + (jbase >> 2) + j4];
            *(float4*)&Ws[kk][j4 * 4] = w;
        }
        // A tile transposed: thread group reads consecutive k (coalesced)
#pragma unroll
        for (int s = 0; s < 4; s++) {
            int lin = s * 256 + tid;
            int bb = lin >> 5, kk = lin & 31;
            int k = k0 + kk;
            As[bb][kk] = (k < Hq) ? h0[bb * Hq + k] : x[bb * Dq + (k - Hq)];
        }
        __syncthreads();
#pragma unroll
        for (int kk = 0; kk < 32; kk++) {
            float4 w = *(const float4*)&Ws[kk][tj * 4];
            float a0 = As[tb * 4 + 0][kk];   // broadcast within warp
            float a1 = As[tb * 4 + 1][kk];
            float a2 = As[tb * 4 + 2][kk];
            float a3 = As[tb * 4 + 3][kk];
            acc[0][0] += a0*w.x; acc[0][1] += a0*w.y; acc[0][2] += a0*w.z; acc[0][3] += a0*w.w;
            acc[1][0] += a1*w.x; acc[1][1] += a1*w.y; acc[1][2] += a1*w.z; acc[1][3] += a1*w.w;
            acc[2][0] += a2*w.x; acc[2][1] += a2*w.y; acc[2][2] += a2*w.z; acc[2][3] += a2*w.w;
            acc[3][0] += a3*w.x; acc[3][1] += a3*w.y; acc[3][2] += a3*w.z; acc[3][3] += a3*w.w;
        }
    }

    float* outp = g_part[ks];
#pragma unroll
    for (int bb = 0; bb < 4; bb++) {
        int b = tb * 4 + bb;
        int base = b * FOURH + jbase + tj * 4;
        *(float4*)&outp[base] = make_float4(acc[bb][0], acc[bb][1], acc[bb][2], acc[bb][3]);
    }
}

// ---------------------------------------------------------------------------
// K_plastic: occupancy-first streaming (hebb-shaped).
// partial[b,sp,h] = sum_{i in 16-chunk sp} h0[b,i]*alpha[i,h]*Hebb0[b,i,h]
// 2-row body -> 4 float4 loads in flight; (256,5) leaves 51 regs so ptxas
// keeps the batch intact (R3/R6 lesson: 42 regs forces rematerialization).
// ---------------------------------------------------------------------------
__global__ __launch_bounds__(256, 5)
void k_plastic(const float* __restrict__ h0, const float* __restrict__ alpha,
               const float* __restrict__ Hebb0)
{
    const int b  = blockIdx.x >> 6;
    const int sp = blockIdx.x & 63;
    const int i0 = sp * PCHUNK;
    const int t  = threadIdx.x;

    const float4* Ap  = (const float4*)(alpha + (size_t)i0 * Hq) + t;
    const float4* Hp  = (const float4*)(Hebb0 + ((size_t)b * Hq + i0) * Hq) + t;
    const float*  h0p = h0 + b * Hq + i0;

    float4 acc = make_float4(0.f, 0.f, 0.f, 0.f);
#pragma unroll 1
    for (int i = 0; i < PCHUNK; i += 2) {
        float4 a0 = Ap[(size_t)(i + 0) * 256];
        float4 v0 = Hp[(size_t)(i + 0) * 256];
        float4 a1 = Ap[(size_t)(i + 1) * 256];
        float4 v1 = Hp[(size_t)(i + 1) * 256];
        float s0 = h0p[i + 0];
        float s1 = h0p[i + 1];
        acc.x = fmaf(s0, a0.x * v0.x, acc.x);
        acc.y = fmaf(s0, a0.y * v0.y, acc.y);
        acc.z = fmaf(s0, a0.z * v0.z, acc.z);
        acc.w = fmaf(s0, a0.w * v0.w, acc.w);
        acc.x = fmaf(s1, a1.x * v1.x, acc.x);
        acc.y = fmaf(s1, a1.y * v1.y, acc.y);
        acc.z = fmaf(s1, a1.z * v1.z, acc.z);
        acc.w = fmaf(s1, a1.w * v1.w, acc.w);
    }
    ((float4*)(g_plastic_part + (size_t)blockIdx.x * Hq))[t] = acc;
}

// ---------------------------------------------------------------------------
// K2: pointwise gates -> h1, c1, tanh_g
// ---------------------------------------------------------------------------
__global__ __launch_bounds__(256)
void pointwise_kernel(const float* __restrict__ c0, const float* __restrict__ bias,
                      float* __restrict__ out)
{
    const int idx = blockIdx.x * 256 + threadIdx.x;   // 0..32767
    const int b = idx >> 10, h = idx & 1023;

    float g4[4];
#pragma unroll
    for (int c = 0; c < 4; c++) {
        float v = bias[c * Hq + h];
        int base = b * FOURH + c * Hq + h;
#pragma unroll
        for (int s = 0; s < KSPLIT; s++) v += g_part[s][base];
        g4[c] = v;
    }
    float pl = 0.f;
#pragma unroll
    for (int s = 0; s < PSPLIT; s++)
        pl += g_plastic_part[(size_t)(b * PSPLIT + s) * Hq + h];
    g4[3] += pl;

    float fg = 1.f / (1.f + expf(-g4[0]));
    float ig = 1.f / (1.f + expf(-g4[1]));
    float og = 1.f / (1.f + expf(-g4[2]));
    float tg = tanhf(g4[3]);
    float c1 = fg * c0[idx] + ig * tg;
    float h1 = og * tanhf(c1);

    out[idx]           = h1;  // h1 block
    out[Bq * Hq + idx] = c1;  // c1 block
    g_tanhg[idx] = tg;
}

// ---------------------------------------------------------------------------
// K3: Hebb1[b,h,i] = clip(Hebb0[b,h,i] + eta*h0[b,h]*tanh_g[b,i], -1, 1)
// 4 rows per block, float4, streaming hints, reversed order for L2 tail reuse
// (plastic ends hot on high-b slices; reversed hebb starts there).
// ---------------------------------------------------------------------------
__global__ __launch_bounds__(256)
void hebb_kernel(const float* __restrict__ Hebb0, const float* __restrict__ h0,
                 const float* __restrict__ eta, float* __restrict__ HebbOut)
{
    const int r0 = (Bq * Hq - 4) - blockIdx.x * 4;   // reversed, 4-row group
    const int b  = r0 >> 10;
    const float e = eta[0];
    const int t = threadIdx.x;

    float4 tv = ((const float4*)(g_tanhg + (size_t)b * Hq))[t];

    const float4* in4 = (const float4*)(Hebb0   + (size_t)r0 * Hq) + t;
    float4*       o4  = (float4*)      (HebbOut + (size_t)r0 * Hq) + t;

    float c0f = e * h0[r0 + 0];
    float c1f = e * h0[r0 + 1];
    float c2f = e * h0[r0 + 2];
    float c3f = e * h0[r0 + 3];

    float4 v0 = __ldcs(in4 + 0 * 256);
    float4 v1 = __ldcs(in4 + 1 * 256);
    float4 v2 = __ldcs(in4 + 2 * 256);
    float4 v3 = __ldcs(in4 + 3 * 256);

    float4 o;
    o.x = fminf(1.f, fmaxf(-1.f, fmaf(c0f, tv.x, v0.x)));
    o.y = fminf(1.f, fmaxf(-1.f, fmaf(c0f, tv.y, v0.y)));
    o.z = fminf(1.f, fmaxf(-1.f, fmaf(c0f, tv.z, v0.z)));
    o.w = fminf(1.f, fmaxf(-1.f, fmaf(c0f, tv.w, v0.w)));
    __stcs(o4 + 0 * 256, o);
    o.x = fminf(1.f, fmaxf(-1.f, fmaf(c1f, tv.x, v1.x)));
    o.y = fminf(1.f, fmaxf(-1.f, fmaf(c1f, tv.y, v1.y)));
    o.z = fminf(1.f, fmaxf(-1.f, fmaf(c1f, tv.z, v1.z)));
    o.w = fminf(1.f, fmaxf(-1.f, fmaf(c1f, tv.w, v1.w)));
    __stcs(o4 + 1 * 256, o);
    o.x = fminf(1.f, fmaxf(-1.f, fmaf(c2f, tv.x, v2.x)));
    o.y = fminf(1.f, fmaxf(-1.f, fmaf(c2f, tv.y, v2.y)));
    o.z = fminf(1.f, fmaxf(-1.f, fmaf(c2f, tv.z, v2.z)));
    o.w = fminf(1.f, fmaxf(-1.f, fmaf(c2f, tv.w, v2.w)));
    __stcs(o4 + 2 * 256, o);
    o.x = fminf(1.f, fmaxf(-1.f, fmaf(c3f, tv.x, v3.x)));
    o.y = fminf(1.f, fmaxf(-1.f, fmaf(c3f, tv.y, v3.y)));
    o.z = fminf(1.f, fmaxf(-1.f, fmaf(c3f, tv.z, v3.z)));
    o.w = fminf(1.f, fmaxf(-1.f, fmaf(c3f, tv.w, v3.w)));
    __stcs(o4 + 3 * 256, o);
}

// ---------------------------------------------------------------------------
// Inputs: x, h0, c0, Hebb0, weight_h, weight_x, bias, alpha, eta
// Output: [h1 (B*H) | c1 (B*H) | Hebb1 (B*H*H)] float32
// ---------------------------------------------------------------------------
extern "C" void kernel_launch(void* const* d_in, const int* in_sizes, int n_in,
                              void* d_out, int out_size)
{
    const float* x     = (const float*)d_in[0];
    const float* h0    = (const float*)d_in[1];
    const float* c0    = (const float*)d_in[2];
    const float* Hebb0 = (const float*)d_in[3];
    const float* Wh    = (const float*)d_in[4];
    const float* Wx    = (const float*)d_in[5];
    const float* bias  = (const float*)d_in[6];
    const float* alpha = (const float*)d_in[7];
    const float* eta   = (const float*)d_in[8];
    float* out = (float*)d_out;

    k_gemm<<<NGEMM, 256>>>(x, h0, Wh, Wx);
    k_plastic<<<NPLAST, 256>>>(h0, alpha, Hebb0);
    pointwise_kernel<<<(Bq * Hq) / 256, 256>>>(c0, bias, out);
    hebb_kernel<<<(Bq * Hq) / 4, 256>>>(Hebb0, h0, eta, out + 2 * Bq * Hq);
}